// round 8
// baseline (speedup 1.0000x reference)
#include <cuda_runtime.h>
#include <cuda_bf16.h>
#include <cstdint>

// G=1024 groups (1 CTA each), K=16 agents, T=32, D=64.
// out[n,t,0:64]=group mean of h ; out[n,t,64:128]=h ; h=fc2(relu(LN(fc1(x))))
// mma.sync m16n8k16 bf16, 3-term hi/lo truncation split.
// Split-N warp pairs: each 16-row stripe handled by 2 warps (32 cols each)
// -> ~84 regs/thread -> 3 CTAs/SM (24 warps).
#define GRPS 1024

// smem byte offsets
#define OFF_W1H  0
#define OFF_W1L  8192
#define OFF_W2H  16384
#define OFF_W2L  24576
#define OFF_ACTH 32768     // 4 stripes x 16 rows x 128B
#define OFF_ACTL 40960
#define OFF_LN   49152     // [4 sp][16 rows][2 halves] float2 = 1KB
#define OFF_B1   50176
#define OFF_B2   50432
#define OFF_LNW  50688
#define OFF_LNB  50944
#define SMEM_BYTES 51200
// post-loop aliases (weights dead):
#define OFF_RED   0        // [64][64] f32, swizzled, 16KB
#define OFF_MEANS 16384    // [32][64] f32, 8KB

__device__ __forceinline__ uint32_t smem_u32(const void* p) {
    uint32_t a;
    asm("{ .reg .u64 t; cvta.to.shared.u64 t, %1; cvt.u32.u64 %0, t; }" : "=r"(a) : "l"(p));
    return a;
}
__device__ __forceinline__ uint32_t bf2pack(float lo, float hi) {
    uint32_t r; asm("cvt.rn.bf16x2.f32 %0, %1, %2;" : "=r"(r) : "f"(hi), "f"(lo)); return r;
}
__device__ __forceinline__ void ldmx4(uint32_t addr, uint32_t* r) {
    asm volatile("ldmatrix.sync.aligned.m8n8.x4.shared.b16 {%0,%1,%2,%3}, [%4];"
                 : "=r"(r[0]), "=r"(r[1]), "=r"(r[2]), "=r"(r[3]) : "r"(addr));
}
__device__ __forceinline__ void mma_bf16(float* c, const uint32_t* a,
                                         uint32_t b0, uint32_t b1) {
    asm volatile(
        "mma.sync.aligned.m16n8k16.row.col.f32.bf16.bf16.f32 "
        "{%0,%1,%2,%3}, {%4,%5,%6,%7}, {%8,%9}, {%0,%1,%2,%3};"
        : "+f"(c[0]), "+f"(c[1]), "+f"(c[2]), "+f"(c[3])
        : "r"(a[0]), "r"(a[1]), "r"(a[2]), "r"(a[3]), "r"(b0), "r"(b1));
}
// truncation split: hi = top 16 bits (PRMT pack), lo = exact remainder -> bf16
__device__ __forceinline__ void split2(float x0, float x1, uint32_t& hi, uint32_t& lo) {
    uint32_t u0 = __float_as_uint(x0), u1 = __float_as_uint(x1);
    hi = __byte_perm(u0, u1, 0x7632);
    float h0 = __uint_as_float(u0 & 0xffff0000u);
    float h1 = __uint_as_float(u1 & 0xffff0000u);
    lo = bf2pack(x0 - h0, x1 - h1);
}
__device__ __forceinline__ void split_store8(char* sm, int offH, int offL,
                                             int row, int ch, float4 a, float4 b) {
    float f[8] = {a.x, a.y, a.z, a.w, b.x, b.y, b.z, b.w};
    uint4 vh, vl;
    split2(f[0], f[1], vh.x, vl.x); split2(f[2], f[3], vh.y, vl.y);
    split2(f[4], f[5], vh.z, vl.z); split2(f[6], f[7], vh.w, vl.w);
    int bo = row * 128 + ((ch ^ (row & 7)) << 4);
    *(uint4*)(sm + offH + bo) = vh;
    *(uint4*)(sm + offL + bo) = vl;
}
#define BARP(id) asm volatile("bar.sync %0, 64;" :: "r"(id) : "memory")

// 16x32 stripe-half GEMM vs weights (2 n16 blocks at wH/wL), register A.
__device__ __forceinline__ void gemm32r(const uint32_t ah[4][4], const uint32_t al[4][4],
                                        uint32_t wH, uint32_t wL,
                                        uint32_t lhalf, uint32_t lxor,
                                        float c[4][4]) {
    #pragma unroll
    for (int kk = 0; kk < 4; kk++) {
        uint32_t co = ((((uint32_t)(kk << 1) + lhalf) ^ lxor) << 4);
        #pragma unroll
        for (int j = 0; j < 2; j++) {
            uint32_t bh[4], bl[4];
            ldmx4(wH + j * 2048 + co, bh);
            ldmx4(wL + j * 2048 + co, bl);
            mma_bf16(c[2*j],   ah[kk], bh[0], bh[2]);
            mma_bf16(c[2*j+1], ah[kk], bh[1], bh[3]);
            mma_bf16(c[2*j],   ah[kk], bl[0], bl[2]);
            mma_bf16(c[2*j+1], ah[kk], bl[1], bl[3]);
            mma_bf16(c[2*j],   al[kk], bh[0], bh[2]);
            mma_bf16(c[2*j+1], al[kk], bh[1], bh[3]);
        }
    }
}

__global__ void __launch_bounds__(256, 3)
subgraph_mma_kernel(const float* __restrict__ x,
                    const float* __restrict__ w1g, const float* __restrict__ b1g,
                    const float* __restrict__ lnwg, const float* __restrict__ lnbg,
                    const float* __restrict__ w2g, const float* __restrict__ b2g,
                    float* __restrict__ out) {
    extern __shared__ char sm[];
    const uint32_t smb = smem_u32(sm);
    const int tid = threadIdx.x, wid = tid >> 5, lane = tid & 31;
    const int g = blockIdx.x;

    // ---- stage weights (bf16 hi/lo, swizzled) + biases ----
    #pragma unroll
    for (int v = 0; v < 2; v++) {
        int lin = tid + v * 256;
        int row = lin >> 3, ch = lin & 7;
        const float4* p1 = (const float4*)(w1g + row * 64 + ch * 8);
        const float4* p2 = (const float4*)(w2g + row * 64 + ch * 8);
        split_store8(sm, OFF_W1H, OFF_W1L, row, ch, p1[0], p1[1]);
        split_store8(sm, OFF_W2H, OFF_W2L, row, ch, p2[0], p2[1]);
    }
    if (tid < 64) {
        ((float*)(sm + OFF_B1))[tid]  = b1g[tid];
        ((float*)(sm + OFF_B2))[tid]  = b2g[tid];
        ((float*)(sm + OFF_LNW))[tid] = lnwg[tid];
        ((float*)(sm + OFF_LNB))[tid] = lnbg[tid];
    }
    __syncthreads();

    const int sp = wid >> 1, nh = wid & 1;           // stripe, column half
    const int r0 = sp * 16;
    const uint32_t lrow  = (uint32_t)((((lane >> 3) & 1) << 3) + (lane & 7));
    const uint32_t lhalf = (uint32_t)(lane >> 4);
    const uint32_t lxor  = (uint32_t)(lane & 7);
    const uint32_t w1B = smb + OFF_W1H + nh * 4096 + lrow * 128;   // W1L = +8192
    const uint32_t w2B = smb + OFF_W2H + nh * 4096 + lrow * 128;
    const uint32_t aB  = smb + OFF_ACTH + sp * 2048 + lrow * 128;  // ACTL = +8192

    const int i0 = lane >> 2, m = lane & 3;
    const float* xg   = x   + (size_t)g * (512 * 64);
    float*       outg = out + (size_t)g * (512 * 128);
    const float2* b1v = (const float2*)(sm + OFF_B1);
    const float2* b2v = (const float2*)(sm + OFF_B2);
    const float2* lw2 = (const float2*)(sm + OFF_LNW);
    const float2* lb2 = (const float2*)(sm + OFF_LNB);

    asm volatile("prefetch.global.L1 [%0];" :: "l"(xg + (size_t)tid * 16));

    float rs[16];
    #pragma unroll
    for (int i = 0; i < 16; i++) rs[i] = 0.f;

    #pragma unroll 1
    for (int mt = 0; mt < 8; mt++) {
        const int rowA = mt * 64 + r0 + i0;
        const float* pa = xg + (size_t)rowA * 64;
        const float* pb = pa + 8 * 64;

        // ---- GEMM1 A fragments straight from gmem ----
        uint32_t ah[4][4], al[4][4];
        #pragma unroll
        for (int kk = 0; kk < 4; kk++) {
            float2 v00 = *(const float2*)(pa + kk * 16 + m * 2);
            float2 v10 = *(const float2*)(pb + kk * 16 + m * 2);
            float2 v01 = *(const float2*)(pa + kk * 16 + 8 + m * 2);
            float2 v11 = *(const float2*)(pb + kk * 16 + 8 + m * 2);
            split2(v00.x, v00.y, ah[kk][0], al[kk][0]);
            split2(v10.x, v10.y, ah[kk][1], al[kk][1]);
            split2(v01.x, v01.y, ah[kk][2], al[kk][2]);
            split2(v11.x, v11.y, ah[kk][3], al[kk][3]);
        }
        if (mt < 7)
            asm volatile("prefetch.global.L1 [%0];"
                         :: "l"(xg + (size_t)(mt + 1) * 4096 + (size_t)tid * 16));

        // ---- GEMM1 (this warp's 32 cols) ----
        float c[4][4];
        #pragma unroll
        for (int i = 0; i < 4; i++)
            #pragma unroll
            for (int j = 0; j < 4; j++) c[i][j] = 0.f;
        gemm32r(ah, al, w1B, w1B + 8192, lhalf, lxor, c);

        // ---- bias + partial LN stats ----
        float s0 = 0.f, q0 = 0.f, s1 = 0.f, q1 = 0.f;
        #pragma unroll
        for (int ci = 0; ci < 4; ci++) {
            int n8 = 4 * nh + ci;
            float2 bb = b1v[n8 * 4 + m];
            c[ci][0] += bb.x; c[ci][1] += bb.y;
            c[ci][2] += bb.x; c[ci][3] += bb.y;
            s0 += c[ci][0] + c[ci][1]; q0 += c[ci][0]*c[ci][0] + c[ci][1]*c[ci][1];
            s1 += c[ci][2] + c[ci][3]; q1 += c[ci][2]*c[ci][2] + c[ci][3]*c[ci][3];
        }
        s0 += __shfl_xor_sync(0xffffffffu, s0, 1); s0 += __shfl_xor_sync(0xffffffffu, s0, 2);
        q0 += __shfl_xor_sync(0xffffffffu, q0, 1); q0 += __shfl_xor_sync(0xffffffffu, q0, 2);
        s1 += __shfl_xor_sync(0xffffffffu, s1, 1); s1 += __shfl_xor_sync(0xffffffffu, s1, 2);
        q1 += __shfl_xor_sync(0xffffffffu, q1, 1); q1 += __shfl_xor_sync(0xffffffffu, q1, 2);

        // ---- exchange half-row stats with pair warp (generic pointers!) ----
        if (m == 0) {
            *(float2*)(sm + OFF_LN + sp * 256 + i0 * 16 + nh * 8)       = make_float2(s0, q0);
            *(float2*)(sm + OFF_LN + sp * 256 + i0 * 16 + nh * 8 + 128) = make_float2(s1, q1);
        }
        BARP(sp + 1);
        {
            float2 o0 = *(const float2*)(sm + OFF_LN + sp * 256 + i0 * 16 + (1 - nh) * 8);
            float2 o1 = *(const float2*)(sm + OFF_LN + sp * 256 + i0 * 16 + (1 - nh) * 8 + 128);
            s0 += o0.x; q0 += o0.y; s1 += o1.x; q1 += o1.y;
        }
        float mu0 = s0 * (1.f/64.f), var0 = q0 * (1.f/64.f) - mu0*mu0;
        float mu1 = s1 * (1.f/64.f), var1 = q1 * (1.f/64.f) - mu1*mu1;
        float inv0 = rsqrtf(var0 + 1e-5f), inv1 = rsqrtf(var1 + 1e-5f);

        // ---- LN*w+b, ReLU, split, stage act halves into smem ----
        #pragma unroll
        for (int ci = 0; ci < 4; ci++) {
            int n8 = 4 * nh + ci;
            float2 lwv = lw2[n8 * 4 + m], lbv = lb2[n8 * 4 + m];
            float a00 = fmaxf(fmaf((c[ci][0] - mu0) * inv0, lwv.x, lbv.x), 0.f);
            float a01 = fmaxf(fmaf((c[ci][1] - mu0) * inv0, lwv.y, lbv.y), 0.f);
            float a10 = fmaxf(fmaf((c[ci][2] - mu1) * inv1, lwv.x, lbv.x), 0.f);
            float a11 = fmaxf(fmaf((c[ci][3] - mu1) * inv1, lwv.y, lbv.y), 0.f);
            uint32_t hi0, lo0, hi1, lo1;
            split2(a00, a01, hi0, lo0);
            split2(a10, a11, hi1, lo1);
            int bo = sp * 2048 + i0 * 128 + ((n8 ^ (i0 & 7)) << 4) + m * 4;
            *(uint32_t*)(sm + OFF_ACTH + bo)        = hi0;
            *(uint32_t*)(sm + OFF_ACTL + bo)        = lo0;
            *(uint32_t*)(sm + OFF_ACTH + bo + 1024) = hi1;   // row +8
            *(uint32_t*)(sm + OFF_ACTL + bo + 1024) = lo1;
        }
        BARP(sp + 1);

        // ---- GEMM2 A fragments from the full act stripe ----
        #pragma unroll
        for (int kk = 0; kk < 4; kk++) {
            uint32_t co = ((((uint32_t)(kk << 1) + lhalf) ^ lxor) << 4);
            ldmx4(aB + co,        ah[kk]);
            ldmx4(aB + 8192 + co, al[kk]);
        }
        #pragma unroll
        for (int i = 0; i < 4; i++)
            #pragma unroll
            for (int j = 0; j < 4; j++) c[i][j] = 0.f;
        gemm32r(ah, al, w2B, w2B + 8192, lhalf, lxor, c);

        // ---- bias, agent-sum accumulate, direct h store ----
        #pragma unroll
        for (int ci = 0; ci < 4; ci++) {
            int n8 = 4 * nh + ci;
            float2 bb = b2v[n8 * 4 + m];
            float v00 = c[ci][0] + bb.x, v01 = c[ci][1] + bb.y;
            float v10 = c[ci][2] + bb.x, v11 = c[ci][3] + bb.y;
            rs[ci*4+0] += v00; rs[ci*4+1] += v01;
            rs[ci*4+2] += v10; rs[ci*4+3] += v11;
            int col0 = n8 * 8 + m * 2;
            *(float2*)(outg + (size_t)rowA       * 128 + 64 + col0) = make_float2(v00, v01);
            *(float2*)(outg + (size_t)(rowA + 8) * 128 + 64 + col0) = make_float2(v10, v11);
        }
    }

    // ---- agent-sum reduction (RED aliases dead weight tiles) ----
    __syncthreads();
    #pragma unroll
    for (int ci = 0; ci < 4; ci++) {
        int n8 = 4 * nh + ci;
        int col0 = n8 * 8 + m * 2;
        int rA = r0 + i0, rB = rA + 8;
        uint32_t oA = (uint32_t)(rA * 256 + (((col0 >> 2) ^ (rA & 15)) << 4) + (col0 & 3) * 4);
        uint32_t oB = (uint32_t)(rB * 256 + (((col0 >> 2) ^ (rB & 15)) << 4) + (col0 & 3) * 4);
        *(float2*)(sm + OFF_RED + oA) = make_float2(rs[ci*4+0], rs[ci*4+1]);
        *(float2*)(sm + OFF_RED + oB) = make_float2(rs[ci*4+2], rs[ci*4+3]);
    }
    __syncthreads();
    {
        int t = tid >> 3, cq = (tid & 7) * 8;
        float* means = (float*)(sm + OFF_MEANS);
        #pragma unroll
        for (int e = 0; e < 8; e++) {
            int cc = cq + e;
            int r1 = t, r2 = t + 32;
            float v1 = *(const float*)(sm + OFF_RED + r1 * 256
                        + (((cc >> 2) ^ (r1 & 15)) << 4) + (cc & 3) * 4);
            float v2 = *(const float*)(sm + OFF_RED + r2 * 256
                        + (((cc >> 2) ^ (r2 & 15)) << 4) + (cc & 3) * 4);
            means[t * 64 + cc] = (v1 + v2) * 0.0625f;
        }
    }
    __syncthreads();
    // ---- broadcast group means to all 16 agents ----
    #pragma unroll 1
    for (int ag = 0; ag < 16; ag++) {
        #pragma unroll
        for (int v = 0; v < 2; v++) {
            int f = tid + v * 256;
            int t = f >> 4, c16 = f & 15;
            float4 mvv = *(const float4*)(sm + OFF_MEANS + (t * 64 + c16 * 4) * 4);
            *(float4*)(outg + (size_t)(ag * 32 + t) * 128 + c16 * 4) = mvv;
        }
    }
}

extern "C" void kernel_launch(void* const* d_in, const int* in_sizes, int n_in,
                              void* d_out, int out_size) {
    const float* x    = (const float*)d_in[0];
    const float* fc1w = (const float*)d_in[3];
    const float* fc1b = (const float*)d_in[4];
    const float* lnw  = (const float*)d_in[5];
    const float* lnb  = (const float*)d_in[6];
    const float* fc2w = (const float*)d_in[7];
    const float* fc2b = (const float*)d_in[8];
    float* out = (float*)d_out;

    cudaFuncSetAttribute(subgraph_mma_kernel,
                         cudaFuncAttributeMaxDynamicSharedMemorySize, SMEM_BYTES);
    subgraph_mma_kernel<<<GRPS, 256, SMEM_BYTES>>>(x, fc1w, fc1b, lnw, lnb, fc2w, fc2b, out);
}

// round 9
// speedup vs baseline: 1.3607x; 1.3607x over previous
#include <cuda_runtime.h>
#include <cuda_fp16.h>
#include <cstdint>

// G=1024 groups (1 CTA each), K=16 agents, T=32, D=64.
// out[n,t,0:64]=group mean of h ; out[n,t,64:128]=h ; h=fc2(relu(LN(fc1(x))))
// mma.sync m16n8k16 fp16, 2-term A-split (A=Ah+Al exact to ~2^-21, W single fp16).
// A frags: GEMM1 from gmem LDG (prefetched); GEMM2 from GEMM1 C-fragments.
#define GRPS 1024

// smem byte offsets
#define OFF_W1  0          // 64 rows x 128B fp16, swizzled
#define OFF_W2  8192
#define OFF_B1  16384
#define OFF_B2  16640
#define OFF_LNW 16896
#define OFF_LNB 17152
#define SMEM_BYTES 17408
// post-loop aliases (weights dead after last GEMM2):
#define OFF_RED   0        // [128 rows][64 cols] f32, 256B rows, chunk-swizzled (32KB)
#define OFF_MEANS 0        // [32][64] f32 (8KB), written after RED consumed
#define SMEM_TOTAL 32768   // max(17408, RED 32KB)

__device__ __forceinline__ uint32_t smem_u32(const void* p) {
    uint32_t a;
    asm("{ .reg .u64 t; cvta.to.shared.u64 t, %1; cvt.u32.u64 %0, t; }" : "=r"(a) : "l"(p));
    return a;
}
__device__ __forceinline__ void ldmx4(uint32_t addr, uint32_t* r) {
    asm volatile("ldmatrix.sync.aligned.m8n8.x4.shared.b16 {%0,%1,%2,%3}, [%4];"
                 : "=r"(r[0]), "=r"(r[1]), "=r"(r[2]), "=r"(r[3]) : "r"(addr));
}
__device__ __forceinline__ void mma_f16(float* c, const uint32_t* a,
                                        uint32_t b0, uint32_t b1) {
    asm volatile(
        "mma.sync.aligned.m16n8k16.row.col.f32.f16.f16.f32 "
        "{%0,%1,%2,%3}, {%4,%5,%6,%7}, {%8,%9}, {%0,%1,%2,%3};"
        : "+f"(c[0]), "+f"(c[1]), "+f"(c[2]), "+f"(c[3])
        : "r"(a[0]), "r"(a[1]), "r"(a[2]), "r"(a[3]), "r"(b0), "r"(b1));
}
// fp16 2-term split: hi = rn(x), lo = rn(x - hi). hi+lo == x to ~2^-21.
__device__ __forceinline__ void split2(float x0, float x1, uint32_t& hi, uint32_t& lo) {
    __half2 h = __floats2half2_rn(x0, x1);
    hi = *(uint32_t*)&h;
    float2 hf = __half22float2(h);
    __half2 l = __floats2half2_rn(x0 - hf.x, x1 - hf.y);
    lo = *(uint32_t*)&l;
}
// convert 8 consecutive fp32 -> one 16B fp16 chunk, swizzled store
__device__ __forceinline__ void conv_store8(char* sm, int off, int row, int ch,
                                            float4 a, float4 b) {
    uint4 v;
    __half2 h0 = __floats2half2_rn(a.x, a.y); v.x = *(uint32_t*)&h0;
    __half2 h1 = __floats2half2_rn(a.z, a.w); v.y = *(uint32_t*)&h1;
    __half2 h2 = __floats2half2_rn(b.x, b.y); v.z = *(uint32_t*)&h2;
    __half2 h3 = __floats2half2_rn(b.z, b.w); v.w = *(uint32_t*)&h3;
    int bo = row * 128 + ((ch ^ (row & 7)) << 4);
    *(uint4*)(sm + off + bo) = v;
}

// 16x64 stripe GEMM vs 64x64 fp16 weights, register A (2 terms).
__device__ __forceinline__ void gemm64r(const uint32_t ah[4][4], const uint32_t al[4][4],
                                        uint32_t wB,
                                        uint32_t lhalf, uint32_t lxor,
                                        float c[8][4]) {
    #pragma unroll
    for (int kk = 0; kk < 4; kk++) {
        uint32_t co = ((((uint32_t)(kk << 1) + lhalf) ^ lxor) << 4);
        #pragma unroll
        for (int np = 0; np < 4; np++) {
            uint32_t b[4];
            ldmx4(wB + np * 2048 + co, b);
            mma_f16(c[2*np],   ah[kk], b[0], b[2]);
            mma_f16(c[2*np+1], ah[kk], b[1], b[3]);
            mma_f16(c[2*np],   al[kk], b[0], b[2]);
            mma_f16(c[2*np+1], al[kk], b[1], b[3]);
        }
    }
}

__global__ void __launch_bounds__(256, 2)
subgraph_mma_kernel(const float* __restrict__ x,
                    const float* __restrict__ w1g, const float* __restrict__ b1g,
                    const float* __restrict__ lnwg, const float* __restrict__ lnbg,
                    const float* __restrict__ w2g, const float* __restrict__ b2g,
                    float* __restrict__ out) {
    extern __shared__ char sm[];
    const uint32_t smb = smem_u32(sm);
    const int tid = threadIdx.x, wid = tid >> 5, lane = tid & 31;
    const int g = blockIdx.x;

    // ---- stage weights (fp16, swizzled) + biases ----
    #pragma unroll
    for (int v = 0; v < 2; v++) {
        int lin = tid + v * 256;          // 0..511 : row 0..63, ch 0..7
        int row = lin >> 3, ch = lin & 7;
        const float4* p1 = (const float4*)(w1g + row * 64 + ch * 8);
        const float4* p2 = (const float4*)(w2g + row * 64 + ch * 8);
        conv_store8(sm, OFF_W1, row, ch, p1[0], p1[1]);
        conv_store8(sm, OFF_W2, row, ch, p2[0], p2[1]);
    }
    if (tid < 64) {
        ((float*)(sm + OFF_B1))[tid]  = b1g[tid];
        ((float*)(sm + OFF_B2))[tid]  = b2g[tid];
        ((float*)(sm + OFF_LNW))[tid] = lnwg[tid];
        ((float*)(sm + OFF_LNB))[tid] = lnbg[tid];
    }
    __syncthreads();

    const int r0 = wid * 16;
    const uint32_t lrow  = (uint32_t)((((lane >> 3) & 1) << 3) + (lane & 7));
    const uint32_t lhalf = (uint32_t)(lane >> 4);
    const uint32_t lxor  = (uint32_t)(lane & 7);
    const uint32_t w1B = smb + OFF_W1 + lrow * 128;
    const uint32_t w2B = smb + OFF_W2 + lrow * 128;

    const int i0 = lane >> 2, m = lane & 3;
    const float* xg   = x   + (size_t)g * (512 * 64);
    float*       outg = out + (size_t)g * (512 * 128);
    const float2* b1v = (const float2*)(sm + OFF_B1);
    const float2* b2v = (const float2*)(sm + OFF_B2);
    const float2* lw2 = (const float2*)(sm + OFF_LNW);
    const float2* lb2 = (const float2*)(sm + OFF_LNB);

    asm volatile("prefetch.global.L1 [%0];" :: "l"(xg + (size_t)tid * 32));

    float rs[32];
    #pragma unroll
    for (int i = 0; i < 32; i++) rs[i] = 0.f;

    #pragma unroll 1
    for (int mt = 0; mt < 4; mt++) {
        const int rowA = mt * 128 + r0 + i0;
        const float* pa = xg + (size_t)rowA * 64;
        const float* pb = pa + 8 * 64;

        // ---- GEMM1 A fragments straight from gmem ----
        float2 xv[2][4][2];
        #pragma unroll
        for (int kk = 0; kk < 4; kk++) {
            #pragma unroll
            for (int j = 0; j < 2; j++) {
                int col = kk * 16 + j * 8 + m * 2;
                xv[0][kk][j] = *(const float2*)(pa + col);
                xv[1][kk][j] = *(const float2*)(pb + col);
            }
        }
        if (mt < 3)
            asm volatile("prefetch.global.L1 [%0];"
                         :: "l"(xg + (size_t)(mt + 1) * 128 * 64 + (size_t)tid * 32));

        uint32_t ah[4][4], al[4][4];
        #pragma unroll
        for (int kk = 0; kk < 4; kk++) {
            split2(xv[0][kk][0].x, xv[0][kk][0].y, ah[kk][0], al[kk][0]);
            split2(xv[1][kk][0].x, xv[1][kk][0].y, ah[kk][1], al[kk][1]);
            split2(xv[0][kk][1].x, xv[0][kk][1].y, ah[kk][2], al[kk][2]);
            split2(xv[1][kk][1].x, xv[1][kk][1].y, ah[kk][3], al[kk][3]);
        }

        // ---- GEMM1 ----
        float c[8][4];
        #pragma unroll
        for (int i = 0; i < 8; i++)
            #pragma unroll
            for (int j = 0; j < 4; j++) c[i][j] = 0.f;
        gemm64r(ah, al, w1B, lhalf, lxor, c);

        // ---- bias (in place) + LayerNorm stats ----
        float s0 = 0.f, q0 = 0.f, s1 = 0.f, q1 = 0.f;
        #pragma unroll
        for (int n8 = 0; n8 < 8; n8++) {
            float2 bb = b1v[n8 * 4 + m];
            c[n8][0] += bb.x; c[n8][1] += bb.y;
            c[n8][2] += bb.x; c[n8][3] += bb.y;
            s0 += c[n8][0] + c[n8][1]; q0 += c[n8][0]*c[n8][0] + c[n8][1]*c[n8][1];
            s1 += c[n8][2] + c[n8][3]; q1 += c[n8][2]*c[n8][2] + c[n8][3]*c[n8][3];
        }
        s0 += __shfl_xor_sync(0xffffffffu, s0, 1); s0 += __shfl_xor_sync(0xffffffffu, s0, 2);
        q0 += __shfl_xor_sync(0xffffffffu, q0, 1); q0 += __shfl_xor_sync(0xffffffffu, q0, 2);
        s1 += __shfl_xor_sync(0xffffffffu, s1, 1); s1 += __shfl_xor_sync(0xffffffffu, s1, 2);
        q1 += __shfl_xor_sync(0xffffffffu, q1, 1); q1 += __shfl_xor_sync(0xffffffffu, q1, 2);
        float mu0 = s0 * (1.f/64.f), var0 = q0 * (1.f/64.f) - mu0*mu0;
        float mu1 = s1 * (1.f/64.f), var1 = q1 * (1.f/64.f) - mu1*mu1;
        float inv0 = rsqrtf(var0 + 1e-5f), inv1 = rsqrtf(var1 + 1e-5f);

        // ---- LN*w+b, ReLU, split -> GEMM2 A fragments (pure registers) ----
        #pragma unroll
        for (int n8 = 0; n8 < 8; n8++) {
            float2 lwv = lw2[n8 * 4 + m], lbv = lb2[n8 * 4 + m];
            float a00 = fmaxf(fmaf((c[n8][0] - mu0) * inv0, lwv.x, lbv.x), 0.f);
            float a01 = fmaxf(fmaf((c[n8][1] - mu0) * inv0, lwv.y, lbv.y), 0.f);
            float a10 = fmaxf(fmaf((c[n8][2] - mu1) * inv1, lwv.x, lbv.x), 0.f);
            float a11 = fmaxf(fmaf((c[n8][3] - mu1) * inv1, lwv.y, lbv.y), 0.f);
            int kk = n8 >> 1, hf = (n8 & 1) * 2;
            split2(a00, a01, ah[kk][hf + 0], al[kk][hf + 0]);
            split2(a10, a11, ah[kk][hf + 1], al[kk][hf + 1]);
        }

        // ---- GEMM2 ----
        #pragma unroll
        for (int i = 0; i < 8; i++)
            #pragma unroll
            for (int j = 0; j < 4; j++) c[i][j] = 0.f;
        gemm64r(ah, al, w2B, lhalf, lxor, c);

        // ---- bias, agent-sum accumulate, direct h store ----
        #pragma unroll
        for (int n8 = 0; n8 < 8; n8++) {
            float2 bb = b2v[n8 * 4 + m];
            float v00 = c[n8][0] + bb.x, v01 = c[n8][1] + bb.y;
            float v10 = c[n8][2] + bb.x, v11 = c[n8][3] + bb.y;
            rs[n8*4+0] += v00; rs[n8*4+1] += v01;
            rs[n8*4+2] += v10; rs[n8*4+3] += v11;
            int col0 = n8 * 8 + m * 2;
            *(float2*)(outg + (size_t)rowA       * 128 + 64 + col0) = make_float2(v00, v01);
            *(float2*)(outg + (size_t)(rowA + 8) * 128 + 64 + col0) = make_float2(v10, v11);
        }
    }

    // ---- cross-warp agent-sum reduction (RED aliases dead weight tiles) ----
    __syncthreads();
    #pragma unroll
    for (int n8 = 0; n8 < 8; n8++) {
        #pragma unroll
        for (int rr = 0; rr < 2; rr++) {
            int row = r0 + i0 + rr * 8;
            int c16 = n8 * 2 + (m >> 1);
            uint32_t byte = (uint32_t)(row * 256 + ((c16 ^ (row & 15)) << 4) + (m & 1) * 8);
            *(float2*)(sm + OFF_RED + byte) =
                make_float2(rs[n8*4 + rr*2], rs[n8*4 + rr*2 + 1]);
        }
    }
    __syncthreads();
    float mv[8];
    int tq = tid >> 3, cq = (tid & 7) * 8;
    #pragma unroll
    for (int e = 0; e < 8; e++) {
        int cc = cq + e;
        float ssum = 0.f;
        #pragma unroll
        for (int a = 0; a < 4; a++) {
            int r = tq + a * 32;
            ssum += *(const float*)(sm + OFF_RED + r * 256
                     + (((cc >> 2) ^ (r & 15)) << 4) + (cc & 3) * 4);
        }
        mv[e] = ssum * 0.0625f;
    }
    __syncthreads();
    {
        float* means = (float*)(sm + OFF_MEANS);
        #pragma unroll
        for (int e = 0; e < 8; e++) means[tq * 64 + cq + e] = mv[e];
    }
    __syncthreads();
    // ---- broadcast group means to all 16 agents ----
    #pragma unroll 1
    for (int ag = 0; ag < 16; ag++) {
        #pragma unroll
        for (int v = 0; v < 2; v++) {
            int f = tid + v * 256;
            int t = f >> 4, c16 = f & 15;
            float4 mvv = *(const float4*)(sm + OFF_MEANS + (t * 64 + c16 * 4) * 4);
            *(float4*)(outg + (size_t)(ag * 32 + t) * 128 + c16 * 4) = mvv;
        }
    }
}

extern "C" void kernel_launch(void* const* d_in, const int* in_sizes, int n_in,
                              void* d_out, int out_size) {
    const float* x    = (const float*)d_in[0];
    const float* fc1w = (const float*)d_in[3];
    const float* fc1b = (const float*)d_in[4];
    const float* lnw  = (const float*)d_in[5];
    const float* lnb  = (const float*)d_in[6];
    const float* fc2w = (const float*)d_in[7];
    const float* fc2b = (const float*)d_in[8];
    float* out = (float*)d_out;

    cudaFuncSetAttribute(subgraph_mma_kernel,
                         cudaFuncAttributeMaxDynamicSharedMemorySize, SMEM_TOTAL);
    subgraph_mma_kernel<<<GRPS, 256, SMEM_TOTAL>>>(x, fc1w, fc1b, lnw, lnb, fc2w, fc2b, out);
}

// round 10
// speedup vs baseline: 1.4807x; 1.0882x over previous
#include <cuda_runtime.h>
#include <cuda_fp16.h>
#include <cstdint>

// G=1024 groups (1 CTA each), K=16 agents, T=32, D=64.
// out[n,t,0:64]=group mean of h ; out[n,t,64:128]=h ; h=fc2(relu(LN(fc1(x))))
// mma.sync m16n8k16 fp16 (single term: A and W both fp16; fp32 accumulate).
// A frags: GEMM1 from gmem LDG (prefetched); GEMM2 from GEMM1 C-fragments.
#define GRPS 1024

// smem byte offsets
#define OFF_W1  0          // 64 rows x 128B fp16, swizzled
#define OFF_W2  8192
#define OFF_B1  16384
#define OFF_B2  16640
#define OFF_LNW 16896
#define OFF_LNB 17152
#define SMEM_BYTES 17408
// post-loop aliases (weights dead after last GEMM2):
#define OFF_RED   0        // [128 rows][64 cols] f32, 256B rows, chunk-swizzled (32KB)
#define OFF_MEANS 0        // [32][64] f32 (8KB), written after RED consumed
#define SMEM_TOTAL 32768

__device__ __forceinline__ uint32_t smem_u32(const void* p) {
    uint32_t a;
    asm("{ .reg .u64 t; cvta.to.shared.u64 t, %1; cvt.u32.u64 %0, t; }" : "=r"(a) : "l"(p));
    return a;
}
__device__ __forceinline__ void ldmx4(uint32_t addr, uint32_t* r) {
    asm volatile("ldmatrix.sync.aligned.m8n8.x4.shared.b16 {%0,%1,%2,%3}, [%4];"
                 : "=r"(r[0]), "=r"(r[1]), "=r"(r[2]), "=r"(r[3]) : "r"(addr));
}
__device__ __forceinline__ void mma_f16(float* c, const uint32_t* a,
                                        uint32_t b0, uint32_t b1) {
    asm volatile(
        "mma.sync.aligned.m16n8k16.row.col.f32.f16.f16.f32 "
        "{%0,%1,%2,%3}, {%4,%5,%6,%7}, {%8,%9}, {%0,%1,%2,%3};"
        : "+f"(c[0]), "+f"(c[1]), "+f"(c[2]), "+f"(c[3])
        : "r"(a[0]), "r"(a[1]), "r"(a[2]), "r"(a[3]), "r"(b0), "r"(b1));
}
__device__ __forceinline__ uint32_t cvt2(float x0, float x1) {
    __half2 h = __floats2half2_rn(x0, x1);
    return *(uint32_t*)&h;
}
// convert 8 consecutive fp32 -> one 16B fp16 chunk, swizzled store
__device__ __forceinline__ void conv_store8(char* sm, int off, int row, int ch,
                                            float4 a, float4 b) {
    uint4 v;
    v.x = cvt2(a.x, a.y); v.y = cvt2(a.z, a.w);
    v.z = cvt2(b.x, b.y); v.w = cvt2(b.z, b.w);
    int bo = row * 128 + ((ch ^ (row & 7)) << 4);
    *(uint4*)(sm + off + bo) = v;
}

// 16x64 stripe GEMM vs 64x64 fp16 weights, register A (single term).
__device__ __forceinline__ void gemm64r(const uint32_t ah[4][4],
                                        uint32_t wB,
                                        uint32_t lhalf, uint32_t lxor,
                                        float c[8][4]) {
    #pragma unroll
    for (int kk = 0; kk < 4; kk++) {
        uint32_t co = ((((uint32_t)(kk << 1) + lhalf) ^ lxor) << 4);
        #pragma unroll
        for (int np = 0; np < 4; np++) {
            uint32_t b[4];
            ldmx4(wB + np * 2048 + co, b);
            mma_f16(c[2*np],   ah[kk], b[0], b[2]);
            mma_f16(c[2*np+1], ah[kk], b[1], b[3]);
        }
    }
}

__global__ void __launch_bounds__(256, 2)
subgraph_mma_kernel(const float* __restrict__ x,
                    const float* __restrict__ w1g, const float* __restrict__ b1g,
                    const float* __restrict__ lnwg, const float* __restrict__ lnbg,
                    const float* __restrict__ w2g, const float* __restrict__ b2g,
                    float* __restrict__ out) {
    extern __shared__ char sm[];
    const uint32_t smb = smem_u32(sm);
    const int tid = threadIdx.x, wid = tid >> 5, lane = tid & 31;
    const int g = blockIdx.x;

    // ---- stage weights (fp16, swizzled) + biases ----
    #pragma unroll
    for (int v = 0; v < 2; v++) {
        int lin = tid + v * 256;          // 0..511 : row 0..63, ch 0..7
        int row = lin >> 3, ch = lin & 7;
        const float4* p1 = (const float4*)(w1g + row * 64 + ch * 8);
        const float4* p2 = (const float4*)(w2g + row * 64 + ch * 8);
        conv_store8(sm, OFF_W1, row, ch, p1[0], p1[1]);
        conv_store8(sm, OFF_W2, row, ch, p2[0], p2[1]);
    }
    if (tid < 64) {
        ((float*)(sm + OFF_B1))[tid]  = b1g[tid];
        ((float*)(sm + OFF_B2))[tid]  = b2g[tid];
        ((float*)(sm + OFF_LNW))[tid] = lnwg[tid];
        ((float*)(sm + OFF_LNB))[tid] = lnbg[tid];
    }
    __syncthreads();

    const int r0 = wid * 16;
    const uint32_t lrow  = (uint32_t)((((lane >> 3) & 1) << 3) + (lane & 7));
    const uint32_t lhalf = (uint32_t)(lane >> 4);
    const uint32_t lxor  = (uint32_t)(lane & 7);
    const uint32_t w1B = smb + OFF_W1 + lrow * 128;
    const uint32_t w2B = smb + OFF_W2 + lrow * 128;

    const int i0 = lane >> 2, m = lane & 3;
    const float* xg   = x   + (size_t)g * (512 * 64);
    float*       outg = out + (size_t)g * (512 * 128);
    const float2* b1v = (const float2*)(sm + OFF_B1);
    const float2* b2v = (const float2*)(sm + OFF_B2);
    const float2* lw2 = (const float2*)(sm + OFF_LNW);
    const float2* lb2 = (const float2*)(sm + OFF_LNB);

    // prefetch tile 0 (whole 32KB: one 128B line per thread)
    asm volatile("prefetch.global.L1 [%0];" :: "l"(xg + (size_t)tid * 32));

    float rs[32];
    #pragma unroll
    for (int i = 0; i < 32; i++) rs[i] = 0.f;

    #pragma unroll 1
    for (int mt = 0; mt < 4; mt++) {
        const int rowA = mt * 128 + r0 + i0;
        const float* pa = xg + (size_t)rowA * 64;
        const float* pb = pa + 8 * 64;

        // ---- GEMM1 A fragments straight from gmem ----
        float2 xv[2][4][2];
        #pragma unroll
        for (int kk = 0; kk < 4; kk++) {
            #pragma unroll
            for (int j = 0; j < 2; j++) {
                int col = kk * 16 + j * 8 + m * 2;
                xv[0][kk][j] = *(const float2*)(pa + col);
                xv[1][kk][j] = *(const float2*)(pb + col);
            }
        }
        if (mt < 3)
            asm volatile("prefetch.global.L1 [%0];"
                         :: "l"(xg + (size_t)(mt + 1) * 128 * 64 + (size_t)tid * 32));

        uint32_t ah[4][4];
        #pragma unroll
        for (int kk = 0; kk < 4; kk++) {
            ah[kk][0] = cvt2(xv[0][kk][0].x, xv[0][kk][0].y);
            ah[kk][1] = cvt2(xv[1][kk][0].x, xv[1][kk][0].y);
            ah[kk][2] = cvt2(xv[0][kk][1].x, xv[0][kk][1].y);
            ah[kk][3] = cvt2(xv[1][kk][1].x, xv[1][kk][1].y);
        }

        // ---- GEMM1 ----
        float c[8][4];
        #pragma unroll
        for (int i = 0; i < 8; i++)
            #pragma unroll
            for (int j = 0; j < 4; j++) c[i][j] = 0.f;
        gemm64r(ah, w1B, lhalf, lxor, c);

        // ---- bias (in place) + LayerNorm stats ----
        float s0 = 0.f, q0 = 0.f, s1 = 0.f, q1 = 0.f;
        #pragma unroll
        for (int n8 = 0; n8 < 8; n8++) {
            float2 bb = b1v[n8 * 4 + m];
            c[n8][0] += bb.x; c[n8][1] += bb.y;
            c[n8][2] += bb.x; c[n8][3] += bb.y;
            s0 += c[n8][0] + c[n8][1]; q0 += c[n8][0]*c[n8][0] + c[n8][1]*c[n8][1];
            s1 += c[n8][2] + c[n8][3]; q1 += c[n8][2]*c[n8][2] + c[n8][3]*c[n8][3];
        }
        s0 += __shfl_xor_sync(0xffffffffu, s0, 1); s0 += __shfl_xor_sync(0xffffffffu, s0, 2);
        q0 += __shfl_xor_sync(0xffffffffu, q0, 1); q0 += __shfl_xor_sync(0xffffffffu, q0, 2);
        s1 += __shfl_xor_sync(0xffffffffu, s1, 1); s1 += __shfl_xor_sync(0xffffffffu, s1, 2);
        q1 += __shfl_xor_sync(0xffffffffu, q1, 1); q1 += __shfl_xor_sync(0xffffffffu, q1, 2);
        float mu0 = s0 * (1.f/64.f), var0 = q0 * (1.f/64.f) - mu0*mu0;
        float mu1 = s1 * (1.f/64.f), var1 = q1 * (1.f/64.f) - mu1*mu1;
        float inv0 = rsqrtf(var0 + 1e-5f), inv1 = rsqrtf(var1 + 1e-5f);

        // ---- LN*w+b, ReLU -> GEMM2 A fragments (pure registers) ----
        #pragma unroll
        for (int n8 = 0; n8 < 8; n8++) {
            float2 lwv = lw2[n8 * 4 + m], lbv = lb2[n8 * 4 + m];
            float a00 = fmaxf(fmaf((c[n8][0] - mu0) * inv0, lwv.x, lbv.x), 0.f);
            float a01 = fmaxf(fmaf((c[n8][1] - mu0) * inv0, lwv.y, lbv.y), 0.f);
            float a10 = fmaxf(fmaf((c[n8][2] - mu1) * inv1, lwv.x, lbv.x), 0.f);
            float a11 = fmaxf(fmaf((c[n8][3] - mu1) * inv1, lwv.y, lbv.y), 0.f);
            int kk = n8 >> 1, hf = (n8 & 1) * 2;
            ah[kk][hf + 0] = cvt2(a00, a01);
            ah[kk][hf + 1] = cvt2(a10, a11);
        }

        // ---- GEMM2 ----
        #pragma unroll
        for (int i = 0; i < 8; i++)
            #pragma unroll
            for (int j = 0; j < 4; j++) c[i][j] = 0.f;
        gemm64r(ah, w2B, lhalf, lxor, c);

        // ---- bias, agent-sum accumulate, direct h store ----
        #pragma unroll
        for (int n8 = 0; n8 < 8; n8++) {
            float2 bb = b2v[n8 * 4 + m];
            float v00 = c[n8][0] + bb.x, v01 = c[n8][1] + bb.y;
            float v10 = c[n8][2] + bb.x, v11 = c[n8][3] + bb.y;
            rs[n8*4+0] += v00; rs[n8*4+1] += v01;
            rs[n8*4+2] += v10; rs[n8*4+3] += v11;
            int col0 = n8 * 8 + m * 2;
            *(float2*)(outg + (size_t)rowA       * 128 + 64 + col0) = make_float2(v00, v01);
            *(float2*)(outg + (size_t)(rowA + 8) * 128 + 64 + col0) = make_float2(v10, v11);
        }
    }

    // ---- cross-warp agent-sum reduction (RED aliases dead weight tiles) ----
    __syncthreads();
    #pragma unroll
    for (int n8 = 0; n8 < 8; n8++) {
        #pragma unroll
        for (int rr = 0; rr < 2; rr++) {
            int row = r0 + i0 + rr * 8;
            int c16 = n8 * 2 + (m >> 1);
            uint32_t byte = (uint32_t)(row * 256 + ((c16 ^ (row & 15)) << 4) + (m & 1) * 8);
            *(float2*)(sm + OFF_RED + byte) =
                make_float2(rs[n8*4 + rr*2], rs[n8*4 + rr*2 + 1]);
        }
    }
    __syncthreads();
    float mv[8];
    int tq = tid >> 3, cq = (tid & 7) * 8;
    #pragma unroll
    for (int e = 0; e < 8; e++) {
        int cc = cq + e;
        float ssum = 0.f;
        #pragma unroll
        for (int a = 0; a < 4; a++) {
            int r = tq + a * 32;
            ssum += *(const float*)(sm + OFF_RED + r * 256
                     + (((cc >> 2) ^ (r & 15)) << 4) + (cc & 3) * 4);
        }
        mv[e] = ssum * 0.0625f;
    }
    __syncthreads();
    {
        float* means = (float*)(sm + OFF_MEANS);
        #pragma unroll
        for (int e = 0; e < 8; e++) means[tq * 64 + cq + e] = mv[e];
    }
    __syncthreads();
    // ---- broadcast group means to all 16 agents ----
    #pragma unroll 1
    for (int ag = 0; ag < 16; ag++) {
        #pragma unroll
        for (int v = 0; v < 2; v++) {
            int f = tid + v * 256;
            int t = f >> 4, c16 = f & 15;
            float4 mvv = *(const float4*)(sm + OFF_MEANS + (t * 64 + c16 * 4) * 4);
            *(float4*)(outg + (size_t)(ag * 32 + t) * 128 + c16 * 4) = mvv;
        }
    }
}

extern "C" void kernel_launch(void* const* d_in, const int* in_sizes, int n_in,
                              void* d_out, int out_size) {
    const float* x    = (const float*)d_in[0];
    const float* fc1w = (const float*)d_in[3];
    const float* fc1b = (const float*)d_in[4];
    const float* lnw  = (const float*)d_in[5];
    const float* lnb  = (const float*)d_in[6];
    const float* fc2w = (const float*)d_in[7];
    const float* fc2b = (const float*)d_in[8];
    float* out = (float*)d_out;

    cudaFuncSetAttribute(subgraph_mma_kernel,
                         cudaFuncAttributeMaxDynamicSharedMemorySize, SMEM_TOTAL);
    subgraph_mma_kernel<<<GRPS, 256, SMEM_TOTAL>>>(x, fc1w, fc1b, lnw, lnb, fc2w, fc2b, out);
}

// round 11
// speedup vs baseline: 1.5905x; 1.0741x over previous
#include <cuda_runtime.h>
#include <cuda_fp16.h>
#include <cstdint>

// G=1024 groups (1 CTA each), K=16 agents, T=32, D=64.
// out[n,t,0:64]=group mean of h ; out[n,t,64:128]=h ; h=fc2(relu(LN(fc1(x))))
// mma.sync m16n8k16 fp16 single-term; warp-private smem staging for coalesced
// x loads and h stores (halves L1TEX line-wavefronts vs fragment-direct I/O).
#define GRPS 1024

// smem byte offsets
#define OFF_W1  0          // 64 rows x 128B fp16, swizzled
#define OFF_W2  8192
#define OFF_AST 16384      // A stage: 8 warps x 16 rows x 128B fp16 = 16KB
#define OFF_HST 32768      // h stage: 8 warps x 16 rows x 256B f32 = 32KB
#define OFF_B1  65536
#define OFF_B2  65792
#define OFF_LNW 66048
#define OFF_LNB 66304
#define SMEM_TOTAL 66560
// post-loop aliases:
#define OFF_RED   OFF_HST  // [128 rows][64 cols] f32, 256B rows, chunk-swizzled
#define OFF_MEANS OFF_AST  // [32][64] f32

__device__ __forceinline__ uint32_t smem_u32(const void* p) {
    uint32_t a;
    asm("{ .reg .u64 t; cvta.to.shared.u64 t, %1; cvt.u32.u64 %0, t; }" : "=r"(a) : "l"(p));
    return a;
}
__device__ __forceinline__ void ldmx4(uint32_t addr, uint32_t* r) {
    asm volatile("ldmatrix.sync.aligned.m8n8.x4.shared.b16 {%0,%1,%2,%3}, [%4];"
                 : "=r"(r[0]), "=r"(r[1]), "=r"(r[2]), "=r"(r[3]) : "r"(addr));
}
__device__ __forceinline__ void mma_f16(float* c, const uint32_t* a,
                                        uint32_t b0, uint32_t b1) {
    asm volatile(
        "mma.sync.aligned.m16n8k16.row.col.f32.f16.f16.f32 "
        "{%0,%1,%2,%3}, {%4,%5,%6,%7}, {%8,%9}, {%0,%1,%2,%3};"
        : "+f"(c[0]), "+f"(c[1]), "+f"(c[2]), "+f"(c[3])
        : "r"(a[0]), "r"(a[1]), "r"(a[2]), "r"(a[3]), "r"(b0), "r"(b1));
}
__device__ __forceinline__ uint32_t cvt2(float x0, float x1) {
    __half2 h = __floats2half2_rn(x0, x1);
    return *(uint32_t*)&h;
}
// convert 8 consecutive fp32 -> one 16B fp16 chunk, swizzled store (weights)
__device__ __forceinline__ void conv_store8(char* sm, int off, int row, int ch,
                                            float4 a, float4 b) {
    uint4 v;
    v.x = cvt2(a.x, a.y); v.y = cvt2(a.z, a.w);
    v.z = cvt2(b.x, b.y); v.w = cvt2(b.z, b.w);
    int bo = row * 128 + ((ch ^ (row & 7)) << 4);
    *(uint4*)(sm + off + bo) = v;
}

// 16x64 stripe GEMM vs 64x64 fp16 weights, register A (single term).
__device__ __forceinline__ void gemm64r(const uint32_t ah[4][4],
                                        uint32_t wB,
                                        uint32_t lhalf, uint32_t lxor,
                                        float c[8][4]) {
    #pragma unroll
    for (int kk = 0; kk < 4; kk++) {
        uint32_t co = ((((uint32_t)(kk << 1) + lhalf) ^ lxor) << 4);
        #pragma unroll
        for (int np = 0; np < 4; np++) {
            uint32_t b[4];
            ldmx4(wB + np * 2048 + co, b);
            mma_f16(c[2*np],   ah[kk], b[0], b[2]);
            mma_f16(c[2*np+1], ah[kk], b[1], b[3]);
        }
    }
}

__global__ void __launch_bounds__(256, 2)
subgraph_mma_kernel(const float* __restrict__ x,
                    const float* __restrict__ w1g, const float* __restrict__ b1g,
                    const float* __restrict__ lnwg, const float* __restrict__ lnbg,
                    const float* __restrict__ w2g, const float* __restrict__ b2g,
                    float* __restrict__ out) {
    extern __shared__ char sm[];
    const uint32_t smb = smem_u32(sm);
    const int tid = threadIdx.x, wid = tid >> 5, lane = tid & 31;
    const int g = blockIdx.x;

    // ---- stage weights (fp16, swizzled) + biases ----
    #pragma unroll
    for (int v = 0; v < 2; v++) {
        int lin = tid + v * 256;          // 0..511 : row 0..63, ch 0..7
        int row = lin >> 3, ch = lin & 7;
        const float4* p1 = (const float4*)(w1g + row * 64 + ch * 8);
        const float4* p2 = (const float4*)(w2g + row * 64 + ch * 8);
        conv_store8(sm, OFF_W1, row, ch, p1[0], p1[1]);
        conv_store8(sm, OFF_W2, row, ch, p2[0], p2[1]);
    }
    if (tid < 64) {
        ((float*)(sm + OFF_B1))[tid]  = b1g[tid];
        ((float*)(sm + OFF_B2))[tid]  = b2g[tid];
        ((float*)(sm + OFF_LNW))[tid] = lnwg[tid];
        ((float*)(sm + OFF_LNB))[tid] = lnbg[tid];
    }
    __syncthreads();

    const int r0 = wid * 16;
    const uint32_t lrow  = (uint32_t)((((lane >> 3) & 1) << 3) + (lane & 7)); // 0..15
    const uint32_t lhalf = (uint32_t)(lane >> 4);
    const uint32_t lxor  = (uint32_t)(lane & 7);
    const uint32_t w1B = smb + OFF_W1 + lrow * 128;
    const uint32_t w2B = smb + OFF_W2 + lrow * 128;
    const uint32_t aStg = smb + OFF_AST + wid * 2048 + lrow * 128;

    const int i0 = lane >> 2, m = lane & 3;
    const int lrow16 = lane >> 4;        // coalesced I/O: row sub-index
    const int lcol   = lane & 15;        // coalesced I/O: 16B chunk id
    char* aSt = sm + OFF_AST + wid * 2048;
    char* hSt = sm + OFF_HST + wid * 4096;

    const float* xg   = x   + (size_t)g * (512 * 64);
    float*       outg = out + (size_t)g * (512 * 128);
    const float2* b1v = (const float2*)(sm + OFF_B1);
    const float2* b2v = (const float2*)(sm + OFF_B2);
    const float2* lw2 = (const float2*)(sm + OFF_LNW);
    const float2* lb2 = (const float2*)(sm + OFF_LNB);

    // prefetch tile 0
    asm volatile("prefetch.global.L1 [%0];" :: "l"(xg + (size_t)tid * 32));

    float rs[32];
    #pragma unroll
    for (int i = 0; i < 32; i++) rs[i] = 0.f;

    #pragma unroll 1
    for (int mt = 0; mt < 4; mt++) {
        __syncwarp();    // stage buffers free (prev tile's ldmx/LDS complete)

        // ---- coalesced x load (full rows) -> fp16 -> A stage ----
        float4 xf[8];
        #pragma unroll
        for (int u = 0; u < 8; u++) {
            int rowL = u * 2 + lrow16;
            xf[u] = *(const float4*)(xg + (size_t)(mt * 128 + r0 + rowL) * 64 + lcol * 4);
        }
        if (mt < 3)
            asm volatile("prefetch.global.L1 [%0];"
                         :: "l"(xg + (size_t)(mt + 1) * 128 * 64 + (size_t)tid * 32));
        #pragma unroll
        for (int u = 0; u < 8; u++) {
            int rowL = u * 2 + lrow16;
            uint2 hv;
            hv.x = cvt2(xf[u].x, xf[u].y);
            hv.y = cvt2(xf[u].z, xf[u].w);
            *(uint2*)(aSt + rowL * 128 + (((lcol >> 1) ^ (rowL & 7)) << 4) + (lcol & 1) * 8) = hv;
        }
        __syncwarp();

        // ---- GEMM1 A fragments via ldmatrix from A stage ----
        uint32_t ah[4][4];
        #pragma unroll
        for (int kk = 0; kk < 4; kk++) {
            uint32_t co = ((((uint32_t)(kk << 1) + lhalf) ^ lxor) << 4);
            ldmx4(aStg + co, ah[kk]);
        }

        // ---- GEMM1 ----
        float c[8][4];
        #pragma unroll
        for (int i = 0; i < 8; i++)
            #pragma unroll
            for (int j = 0; j < 4; j++) c[i][j] = 0.f;
        gemm64r(ah, w1B, lhalf, lxor, c);

        // ---- bias (in place) + LayerNorm stats ----
        float s0 = 0.f, q0 = 0.f, s1 = 0.f, q1 = 0.f;
        #pragma unroll
        for (int n8 = 0; n8 < 8; n8++) {
            float2 bb = b1v[n8 * 4 + m];
            c[n8][0] += bb.x; c[n8][1] += bb.y;
            c[n8][2] += bb.x; c[n8][3] += bb.y;
            s0 += c[n8][0] + c[n8][1]; q0 += c[n8][0]*c[n8][0] + c[n8][1]*c[n8][1];
            s1 += c[n8][2] + c[n8][3]; q1 += c[n8][2]*c[n8][2] + c[n8][3]*c[n8][3];
        }
        s0 += __shfl_xor_sync(0xffffffffu, s0, 1); s0 += __shfl_xor_sync(0xffffffffu, s0, 2);
        q0 += __shfl_xor_sync(0xffffffffu, q0, 1); q0 += __shfl_xor_sync(0xffffffffu, q0, 2);
        s1 += __shfl_xor_sync(0xffffffffu, s1, 1); s1 += __shfl_xor_sync(0xffffffffu, s1, 2);
        q1 += __shfl_xor_sync(0xffffffffu, q1, 1); q1 += __shfl_xor_sync(0xffffffffu, q1, 2);
        float mu0 = s0 * (1.f/64.f), var0 = q0 * (1.f/64.f) - mu0*mu0;
        float mu1 = s1 * (1.f/64.f), var1 = q1 * (1.f/64.f) - mu1*mu1;
        float inv0 = rsqrtf(var0 + 1e-5f), inv1 = rsqrtf(var1 + 1e-5f);

        // ---- LN*w+b, ReLU -> GEMM2 A fragments (pure registers) ----
        #pragma unroll
        for (int n8 = 0; n8 < 8; n8++) {
            float2 lwv = lw2[n8 * 4 + m], lbv = lb2[n8 * 4 + m];
            float a00 = fmaxf(fmaf((c[n8][0] - mu0) * inv0, lwv.x, lbv.x), 0.f);
            float a01 = fmaxf(fmaf((c[n8][1] - mu0) * inv0, lwv.y, lbv.y), 0.f);
            float a10 = fmaxf(fmaf((c[n8][2] - mu1) * inv1, lwv.x, lbv.x), 0.f);
            float a11 = fmaxf(fmaf((c[n8][3] - mu1) * inv1, lwv.y, lbv.y), 0.f);
            int kk = n8 >> 1, hf = (n8 & 1) * 2;
            ah[kk][hf + 0] = cvt2(a00, a01);
            ah[kk][hf + 1] = cvt2(a10, a11);
        }

        // ---- GEMM2 ----
        #pragma unroll
        for (int i = 0; i < 8; i++)
            #pragma unroll
            for (int j = 0; j < 4; j++) c[i][j] = 0.f;
        gemm64r(ah, w2B, lhalf, lxor, c);

        // ---- bias, agent-sum accumulate, stage h into smem ----
        #pragma unroll
        for (int n8 = 0; n8 < 8; n8++) {
            float2 bb = b2v[n8 * 4 + m];
            float v00 = c[n8][0] + bb.x, v01 = c[n8][1] + bb.y;
            float v10 = c[n8][2] + bb.x, v11 = c[n8][3] + bb.y;
            rs[n8*4+0] += v00; rs[n8*4+1] += v01;
            rs[n8*4+2] += v10; rs[n8*4+3] += v11;
            int ch = n8 * 2 + (m >> 1), off8 = (m & 1) * 8;
            int rA = i0, rB = i0 + 8;
            *(float2*)(hSt + rA * 256 + ((ch ^ (rA & 15)) << 4) + off8) = make_float2(v00, v01);
            *(float2*)(hSt + rB * 256 + ((ch ^ (rB & 15)) << 4) + off8) = make_float2(v10, v11);
        }
        __syncwarp();

        // ---- coalesced h store (full rows) ----
        #pragma unroll
        for (int u = 0; u < 8; u++) {
            int rowL = u * 2 + lrow16;
            float4 hv = *(const float4*)(hSt + rowL * 256 + ((lcol ^ (rowL & 15)) << 4));
            *(float4*)(outg + (size_t)(mt * 128 + r0 + rowL) * 128 + 64 + lcol * 4) = hv;
        }
    }

    // ---- cross-warp agent-sum reduction (RED aliases h stage) ----
    __syncthreads();
    #pragma unroll
    for (int n8 = 0; n8 < 8; n8++) {
        #pragma unroll
        for (int rr = 0; rr < 2; rr++) {
            int row = r0 + i0 + rr * 8;
            int c16 = n8 * 2 + (m >> 1);
            uint32_t byte = (uint32_t)(row * 256 + ((c16 ^ (row & 15)) << 4) + (m & 1) * 8);
            *(float2*)(sm + OFF_RED + byte) =
                make_float2(rs[n8*4 + rr*2], rs[n8*4 + rr*2 + 1]);
        }
    }
    __syncthreads();
    float mv[8];
    int tq = tid >> 3, cq = (tid & 7) * 8;
    #pragma unroll
    for (int e = 0; e < 8; e++) {
        int cc = cq + e;
        float ssum = 0.f;
        #pragma unroll
        for (int a = 0; a < 4; a++) {
            int r = tq + a * 32;
            ssum += *(const float*)(sm + OFF_RED + r * 256
                     + (((cc >> 2) ^ (r & 15)) << 4) + (cc & 3) * 4);
        }
        mv[e] = ssum * 0.0625f;
    }
    __syncthreads();
    {
        float* means = (float*)(sm + OFF_MEANS);
        #pragma unroll
        for (int e = 0; e < 8; e++) means[tq * 64 + cq + e] = mv[e];
    }
    __syncthreads();
    // ---- broadcast group means to all 16 agents ----
    #pragma unroll 1
    for (int ag = 0; ag < 16; ag++) {
        #pragma unroll
        for (int v = 0; v < 2; v++) {
            int f = tid + v * 256;
            int t = f >> 4, c16 = f & 15;
            float4 mvv = *(const float4*)(sm + OFF_MEANS + (t * 64 + c16 * 4) * 4);
            *(float4*)(outg + (size_t)(ag * 32 + t) * 128 + c16 * 4) = mvv;
        }
    }
}

extern "C" void kernel_launch(void* const* d_in, const int* in_sizes, int n_in,
                              void* d_out, int out_size) {
    const float* x    = (const float*)d_in[0];
    const float* fc1w = (const float*)d_in[3];
    const float* fc1b = (const float*)d_in[4];
    const float* lnw  = (const float*)d_in[5];
    const float* lnb  = (const float*)d_in[6];
    const float* fc2w = (const float*)d_in[7];
    const float* fc2b = (const float*)d_in[8];
    float* out = (float*)d_out;

    cudaFuncSetAttribute(subgraph_mma_kernel,
                         cudaFuncAttributeMaxDynamicSharedMemorySize, SMEM_TOTAL);
    subgraph_mma_kernel<<<GRPS, 256, SMEM_TOTAL>>>(x, fc1w, fc1b, lnw, lnb, fc2w, fc2b, out);
}

// round 12
// speedup vs baseline: 1.6310x; 1.0255x over previous
#include <cuda_runtime.h>
#include <cuda_fp16.h>
#include <cstdint>

// G=1024 groups (1 CTA each), K=16 agents, T=32, D=64.
// out[n,t,0:64]=group mean of h ; out[n,t,64:128]=h ; h=fc2(relu(LN(fc1(x))))
// mma.sync m16n8k16 fp16 single-term; warp-private smem staging for coalesced
// x loads and h stores; fused register-resident mean broadcast epilogue.
#define GRPS 1024

// smem byte offsets
#define OFF_W1  0          // 64 rows x 128B fp16, swizzled
#define OFF_W2  8192
#define OFF_AST 16384      // A stage: 8 warps x 16 rows x 128B fp16 = 16KB
#define OFF_HST 32768      // h stage: 8 warps x 16 rows x 256B f32 = 32KB
#define OFF_B1  65536
#define OFF_B2  65792
#define OFF_LNW 66048
#define OFF_LNB 66304
#define SMEM_TOTAL 66560
// post-loop alias:
#define OFF_RED   OFF_HST  // [128 rows][64 cols] f32, 256B rows, chunk-swizzled

__device__ __forceinline__ uint32_t smem_u32(const void* p) {
    uint32_t a;
    asm("{ .reg .u64 t; cvta.to.shared.u64 t, %1; cvt.u32.u64 %0, t; }" : "=r"(a) : "l"(p));
    return a;
}
__device__ __forceinline__ void ldmx4(uint32_t addr, uint32_t* r) {
    asm volatile("ldmatrix.sync.aligned.m8n8.x4.shared.b16 {%0,%1,%2,%3}, [%4];"
                 : "=r"(r[0]), "=r"(r[1]), "=r"(r[2]), "=r"(r[3]) : "r"(addr));
}
__device__ __forceinline__ void mma_f16(float* c, const uint32_t* a,
                                        uint32_t b0, uint32_t b1) {
    asm volatile(
        "mma.sync.aligned.m16n8k16.row.col.f32.f16.f16.f32 "
        "{%0,%1,%2,%3}, {%4,%5,%6,%7}, {%8,%9}, {%0,%1,%2,%3};"
        : "+f"(c[0]), "+f"(c[1]), "+f"(c[2]), "+f"(c[3])
        : "r"(a[0]), "r"(a[1]), "r"(a[2]), "r"(a[3]), "r"(b0), "r"(b1));
}
__device__ __forceinline__ uint32_t cvt2(float x0, float x1) {
    __half2 h = __floats2half2_rn(x0, x1);
    return *(uint32_t*)&h;
}
__device__ __forceinline__ void stcs4(float* p, float4 v) {
    asm volatile("st.global.cs.v4.f32 [%0], {%1,%2,%3,%4};"
                 :: "l"(p), "f"(v.x), "f"(v.y), "f"(v.z), "f"(v.w) : "memory");
}
__device__ __forceinline__ void stcs2(float* p, float2 v) {
    asm volatile("st.global.cs.v2.f32 [%0], {%1,%2};"
                 :: "l"(p), "f"(v.x), "f"(v.y) : "memory");
}
// convert 8 consecutive fp32 -> one 16B fp16 chunk, swizzled store (weights)
__device__ __forceinline__ void conv_store8(char* sm, int off, int row, int ch,
                                            float4 a, float4 b) {
    uint4 v;
    v.x = cvt2(a.x, a.y); v.y = cvt2(a.z, a.w);
    v.z = cvt2(b.x, b.y); v.w = cvt2(b.z, b.w);
    int bo = row * 128 + ((ch ^ (row & 7)) << 4);
    *(uint4*)(sm + off + bo) = v;
}

// 16x64 stripe GEMM vs 64x64 fp16 weights, register A (single term).
__device__ __forceinline__ void gemm64r(const uint32_t ah[4][4],
                                        uint32_t wB,
                                        uint32_t lhalf, uint32_t lxor,
                                        float c[8][4]) {
    #pragma unroll
    for (int kk = 0; kk < 4; kk++) {
        uint32_t co = ((((uint32_t)(kk << 1) + lhalf) ^ lxor) << 4);
        #pragma unroll
        for (int np = 0; np < 4; np++) {
            uint32_t b[4];
            ldmx4(wB + np * 2048 + co, b);
            mma_f16(c[2*np],   ah[kk], b[0], b[2]);
            mma_f16(c[2*np+1], ah[kk], b[1], b[3]);
        }
    }
}

__global__ void __launch_bounds__(256, 2)
subgraph_mma_kernel(const float* __restrict__ x,
                    const float* __restrict__ w1g, const float* __restrict__ b1g,
                    const float* __restrict__ lnwg, const float* __restrict__ lnbg,
                    const float* __restrict__ w2g, const float* __restrict__ b2g,
                    float* __restrict__ out) {
    extern __shared__ char sm[];
    const uint32_t smb = smem_u32(sm);
    const int tid = threadIdx.x, wid = tid >> 5, lane = tid & 31;
    const int g = blockIdx.x;

    // ---- stage weights (fp16, swizzled) + biases ----
    #pragma unroll
    for (int v = 0; v < 2; v++) {
        int lin = tid + v * 256;          // 0..511 : row 0..63, ch 0..7
        int row = lin >> 3, ch = lin & 7;
        const float4* p1 = (const float4*)(w1g + row * 64 + ch * 8);
        const float4* p2 = (const float4*)(w2g + row * 64 + ch * 8);
        conv_store8(sm, OFF_W1, row, ch, p1[0], p1[1]);
        conv_store8(sm, OFF_W2, row, ch, p2[0], p2[1]);
    }
    if (tid < 64) {
        ((float*)(sm + OFF_B1))[tid]  = b1g[tid];
        ((float*)(sm + OFF_B2))[tid]  = b2g[tid];
        ((float*)(sm + OFF_LNW))[tid] = lnwg[tid];
        ((float*)(sm + OFF_LNB))[tid] = lnbg[tid];
    }
    __syncthreads();

    const int r0 = wid * 16;
    const uint32_t lrow  = (uint32_t)((((lane >> 3) & 1) << 3) + (lane & 7)); // 0..15
    const uint32_t lhalf = (uint32_t)(lane >> 4);
    const uint32_t lxor  = (uint32_t)(lane & 7);
    const uint32_t w1B = smb + OFF_W1 + lrow * 128;
    const uint32_t w2B = smb + OFF_W2 + lrow * 128;
    const uint32_t aStg = smb + OFF_AST + wid * 2048 + lrow * 128;

    const int i0 = lane >> 2, m = lane & 3;
    const int lrow16 = lane >> 4;        // coalesced I/O: row sub-index
    const int lcol   = lane & 15;        // coalesced I/O: 16B chunk id
    char* aSt = sm + OFF_AST + wid * 2048;
    char* hSt = sm + OFF_HST + wid * 4096;

    const float* xg   = x   + (size_t)g * (512 * 64);
    float*       outg = out + (size_t)g * (512 * 128);
    const float2* b1v = (const float2*)(sm + OFF_B1);
    const float2* b2v = (const float2*)(sm + OFF_B2);
    const float2* lw2 = (const float2*)(sm + OFF_LNW);
    const float2* lb2 = (const float2*)(sm + OFF_LNB);

    // prefetch tile 0
    asm volatile("prefetch.global.L1 [%0];" :: "l"(xg + (size_t)tid * 32));

    float rs[32];
    #pragma unroll
    for (int i = 0; i < 32; i++) rs[i] = 0.f;

    #pragma unroll 1
    for (int mt = 0; mt < 4; mt++) {
        __syncwarp();    // stage buffers free (prev tile's ldmx/LDS complete)

        // ---- coalesced x load (full rows) -> fp16 -> A stage ----
        float4 xf[8];
        #pragma unroll
        for (int u = 0; u < 8; u++) {
            int rowL = u * 2 + lrow16;
            xf[u] = *(const float4*)(xg + (size_t)(mt * 128 + r0 + rowL) * 64 + lcol * 4);
        }
        if (mt < 3)
            asm volatile("prefetch.global.L1 [%0];"
                         :: "l"(xg + (size_t)(mt + 1) * 128 * 64 + (size_t)tid * 32));
        #pragma unroll
        for (int u = 0; u < 8; u++) {
            int rowL = u * 2 + lrow16;
            uint2 hv;
            hv.x = cvt2(xf[u].x, xf[u].y);
            hv.y = cvt2(xf[u].z, xf[u].w);
            *(uint2*)(aSt + rowL * 128 + (((lcol >> 1) ^ (rowL & 7)) << 4) + (lcol & 1) * 8) = hv;
        }
        __syncwarp();

        // ---- GEMM1 A fragments via ldmatrix from A stage ----
        uint32_t ah[4][4];
        #pragma unroll
        for (int kk = 0; kk < 4; kk++) {
            uint32_t co = ((((uint32_t)(kk << 1) + lhalf) ^ lxor) << 4);
            ldmx4(aStg + co, ah[kk]);
        }

        // ---- GEMM1 ----
        float c[8][4];
        #pragma unroll
        for (int i = 0; i < 8; i++)
            #pragma unroll
            for (int j = 0; j < 4; j++) c[i][j] = 0.f;
        gemm64r(ah, w1B, lhalf, lxor, c);

        // ---- bias (in place) + LayerNorm stats ----
        float s0 = 0.f, q0 = 0.f, s1 = 0.f, q1 = 0.f;
        #pragma unroll
        for (int n8 = 0; n8 < 8; n8++) {
            float2 bb = b1v[n8 * 4 + m];
            c[n8][0] += bb.x; c[n8][1] += bb.y;
            c[n8][2] += bb.x; c[n8][3] += bb.y;
            s0 += c[n8][0] + c[n8][1]; q0 += c[n8][0]*c[n8][0] + c[n8][1]*c[n8][1];
            s1 += c[n8][2] + c[n8][3]; q1 += c[n8][2]*c[n8][2] + c[n8][3]*c[n8][3];
        }
        s0 += __shfl_xor_sync(0xffffffffu, s0, 1); s0 += __shfl_xor_sync(0xffffffffu, s0, 2);
        q0 += __shfl_xor_sync(0xffffffffu, q0, 1); q0 += __shfl_xor_sync(0xffffffffu, q0, 2);
        s1 += __shfl_xor_sync(0xffffffffu, s1, 1); s1 += __shfl_xor_sync(0xffffffffu, s1, 2);
        q1 += __shfl_xor_sync(0xffffffffu, q1, 1); q1 += __shfl_xor_sync(0xffffffffu, q1, 2);
        float mu0 = s0 * (1.f/64.f), var0 = q0 * (1.f/64.f) - mu0*mu0;
        float mu1 = s1 * (1.f/64.f), var1 = q1 * (1.f/64.f) - mu1*mu1;
        float inv0 = rsqrtf(var0 + 1e-5f), inv1 = rsqrtf(var1 + 1e-5f);

        // ---- LN*w+b, ReLU -> GEMM2 A fragments (pure registers) ----
        #pragma unroll
        for (int n8 = 0; n8 < 8; n8++) {
            float2 lwv = lw2[n8 * 4 + m], lbv = lb2[n8 * 4 + m];
            float a00 = fmaxf(fmaf((c[n8][0] - mu0) * inv0, lwv.x, lbv.x), 0.f);
            float a01 = fmaxf(fmaf((c[n8][1] - mu0) * inv0, lwv.y, lbv.y), 0.f);
            float a10 = fmaxf(fmaf((c[n8][2] - mu1) * inv1, lwv.x, lbv.x), 0.f);
            float a11 = fmaxf(fmaf((c[n8][3] - mu1) * inv1, lwv.y, lbv.y), 0.f);
            int kk = n8 >> 1, hf = (n8 & 1) * 2;
            ah[kk][hf + 0] = cvt2(a00, a01);
            ah[kk][hf + 1] = cvt2(a10, a11);
        }

        // ---- GEMM2 ----
        #pragma unroll
        for (int i = 0; i < 8; i++)
            #pragma unroll
            for (int j = 0; j < 4; j++) c[i][j] = 0.f;
        gemm64r(ah, w2B, lhalf, lxor, c);

        // ---- bias, agent-sum accumulate, stage h into smem ----
        #pragma unroll
        for (int n8 = 0; n8 < 8; n8++) {
            float2 bb = b2v[n8 * 4 + m];
            float v00 = c[n8][0] + bb.x, v01 = c[n8][1] + bb.y;
            float v10 = c[n8][2] + bb.x, v11 = c[n8][3] + bb.y;
            rs[n8*4+0] += v00; rs[n8*4+1] += v01;
            rs[n8*4+2] += v10; rs[n8*4+3] += v11;
            int ch = n8 * 2 + (m >> 1), off8 = (m & 1) * 8;
            int rA = i0, rB = i0 + 8;
            *(float2*)(hSt + rA * 256 + ((ch ^ (rA & 15)) << 4) + off8) = make_float2(v00, v01);
            *(float2*)(hSt + rB * 256 + ((ch ^ (rB & 15)) << 4) + off8) = make_float2(v10, v11);
        }
        __syncwarp();

        // ---- coalesced h store (full rows, streaming) ----
        #pragma unroll
        for (int u = 0; u < 8; u++) {
            int rowL = u * 2 + lrow16;
            float4 hv = *(const float4*)(hSt + rowL * 256 + ((lcol ^ (rowL & 15)) << 4));
            stcs4(outg + (size_t)(mt * 128 + r0 + rowL) * 128 + 64 + lcol * 4, hv);
        }
    }

    // ---- cross-warp agent-sum reduction (RED aliases h stage) ----
    __syncthreads();
    #pragma unroll
    for (int n8 = 0; n8 < 8; n8++) {
        #pragma unroll
        for (int rr = 0; rr < 2; rr++) {
            int row = r0 + i0 + rr * 8;
            int c16 = n8 * 2 + (m >> 1);
            uint32_t byte = (uint32_t)(row * 256 + ((c16 ^ (row & 15)) << 4) + (m & 1) * 8);
            *(float2*)(sm + OFF_RED + byte) =
                make_float2(rs[n8*4 + rr*2], rs[n8*4 + rr*2 + 1]);
        }
    }
    __syncthreads();

    // ---- fused reduce + broadcast: registers only, 16 streaming stores ----
    #pragma unroll
    for (int v = 0; v < 2; v++) {
        int f = tid + v * 256;
        int t = f >> 4, c16 = f & 15;
        float4 acc = make_float4(0.f, 0.f, 0.f, 0.f);
        #pragma unroll
        for (int a = 0; a < 4; a++) {
            int r = t + a * 32;
            float4 rv = *(const float4*)(sm + OFF_RED + r * 256 + ((c16 ^ (r & 15)) << 4));
            acc.x += rv.x; acc.y += rv.y; acc.z += rv.z; acc.w += rv.w;
        }
        acc.x *= 0.0625f; acc.y *= 0.0625f; acc.z *= 0.0625f; acc.w *= 0.0625f;
        #pragma unroll
        for (int ag = 0; ag < 16; ag++)
            stcs4(outg + (size_t)(ag * 32 + t) * 128 + c16 * 4, acc);
    }
}

extern "C" void kernel_launch(void* const* d_in, const int* in_sizes, int n_in,
                              void* d_out, int out_size) {
    const float* x    = (const float*)d_in[0];
    const float* fc1w = (const float*)d_in[3];
    const float* fc1b = (const float*)d_in[4];
    const float* lnw  = (const float*)d_in[5];
    const float* lnb  = (const float*)d_in[6];
    const float* fc2w = (const float*)d_in[7];
    const float* fc2b = (const float*)d_in[8];
    float* out = (float*)d_out;

    cudaFuncSetAttribute(subgraph_mma_kernel,
                         cudaFuncAttributeMaxDynamicSharedMemorySize, SMEM_TOTAL);
    subgraph_mma_kernel<<<GRPS, 256, SMEM_TOTAL>>>(x, fc1w, fc1b, lnw, lnb, fc2w, fc2b, out);
}